// round 1
// baseline (speedup 1.0000x reference)
#include <cuda_runtime.h>
#include <math.h>

#define Nn 1024
#define Ff 64
#define LRELU_ALPHA 0.2f
#define NEG_INF -9000000000000000.0f

// scratch (module-load allocated, allowed)
__device__ float g_Wh[Nn * Ff];
__device__ float g_e1[Nn];
__device__ float g_e2[Nn];
__device__ float g_m[Nn];
__device__ float g_is[Nn];

// ---------------------------------------------------------------------------
// k1: Wh = h @ W ; e1 = Wh @ a1 ; e2 = Wh @ a2
// 64 blocks x 256 threads, 16 rows per block.
// ---------------------------------------------------------------------------
__global__ __launch_bounds__(256) void gat_k1(const float* __restrict__ h,
                                              const float* __restrict__ W,
                                              const float* __restrict__ a) {
    __shared__ float Ws[Ff * Ff];        // [k][f]
    __shared__ float hs[16 * 65];        // padded (bank-conflict-free broadcast)
    __shared__ float a1s[Ff], a2s[Ff];
    int t = threadIdx.x;
    int row0 = blockIdx.x * 16;

#pragma unroll
    for (int k = 0; k < 4; k++)
        ((float4*)Ws)[t + k * 256] = ((const float4*)W)[t + k * 256];
#pragma unroll
    for (int k = 0; k < 4; k++) {
        int idx = t + k * 256;           // 0..1023
        int r = idx >> 6, c = idx & 63;
        hs[r * 65 + c] = h[row0 * Ff + idx];
    }
    if (t < Ff) { a1s[t] = a[t]; a2s[t] = a[Ff + t]; }
    __syncthreads();

    int ii = t >> 4;                     // 0..15 (row in block)
    int fi = t & 15;                     // 0..15 (feature quad)
    float4 acc = make_float4(0.f, 0.f, 0.f, 0.f);
#pragma unroll
    for (int k = 0; k < Ff; k++) {
        float hv = hs[ii * 65 + k];
        float4 w4 = ((const float4*)Ws)[k * 16 + fi];
        acc.x += hv * w4.x; acc.y += hv * w4.y;
        acc.z += hv * w4.z; acc.w += hv * w4.w;
    }
    int row = row0 + ii;
    ((float4*)g_Wh)[row * 16 + fi] = acc;

    float4 a14 = ((const float4*)a1s)[fi];
    float4 a24 = ((const float4*)a2s)[fi];
    float p1 = acc.x * a14.x + acc.y * a14.y + acc.z * a14.z + acc.w * a14.w;
    float p2 = acc.x * a24.x + acc.y * a24.y + acc.z * a24.z + acc.w * a24.w;
#pragma unroll
    for (int o = 8; o; o >>= 1) {
        p1 += __shfl_down_sync(0xffffffffu, p1, o, 16);
        p2 += __shfl_down_sync(0xffffffffu, p2, o, 16);
    }
    if (fi == 0) { g_e1[row] = p1; g_e2[row] = p2; }
}

// ---------------------------------------------------------------------------
// k2a: per-row softmax stats. 1024 blocks x 256 threads (4 cols/thread).
// scores stay in registers; m and 1/sum written to scratch.
// ---------------------------------------------------------------------------
__global__ __launch_bounds__(256) void gat_k2a(const int* __restrict__ adj) {
    int i = blockIdx.x, t = threadIdx.x;
    float e1i = g_e1[i];
    int4 av = ((const int4*)(adj + (size_t)i * Nn))[t];
    float4 e2v = ((const float4*)g_e2)[t];

    float s0 = e1i + e2v.x; s0 = (s0 > 0.f) ? s0 : LRELU_ALPHA * s0; if (av.x <= 0) s0 = NEG_INF;
    float s1 = e1i + e2v.y; s1 = (s1 > 0.f) ? s1 : LRELU_ALPHA * s1; if (av.y <= 0) s1 = NEG_INF;
    float s2 = e1i + e2v.z; s2 = (s2 > 0.f) ? s2 : LRELU_ALPHA * s2; if (av.z <= 0) s2 = NEG_INF;
    float s3 = e1i + e2v.w; s3 = (s3 > 0.f) ? s3 : LRELU_ALPHA * s3; if (av.w <= 0) s3 = NEG_INF;

    float mx = fmaxf(fmaxf(s0, s1), fmaxf(s2, s3));
#pragma unroll
    for (int o = 16; o; o >>= 1) mx = fmaxf(mx, __shfl_xor_sync(0xffffffffu, mx, o));

    __shared__ float wmax[8];
    __shared__ float wsum[8];
    __shared__ float bm;
    int w = t >> 5, l = t & 31;
    if (l == 0) wmax[w] = mx;
    __syncthreads();
    if (t < 32) {
        float v = (t < 8) ? wmax[t] : NEG_INF;
#pragma unroll
        for (int o = 4; o; o >>= 1) v = fmaxf(v, __shfl_xor_sync(0xffffffffu, v, o));
        if (t == 0) bm = v;
    }
    __syncthreads();
    float m = bm;
    float sum = __expf(s0 - m) + __expf(s1 - m) + __expf(s2 - m) + __expf(s3 - m);
#pragma unroll
    for (int o = 16; o; o >>= 1) sum += __shfl_xor_sync(0xffffffffu, sum, o);
    if (l == 0) wsum[w] = sum;
    __syncthreads();
    if (t == 0) {
        float s = 0.f;
#pragma unroll
        for (int k = 0; k < 8; k++) s += wsum[k];
        g_m[i] = m;
        g_is[i] = 1.0f / s;
    }
}

// ---------------------------------------------------------------------------
// k2b: out = elu(P @ Wh). 128 blocks x 256 threads, 8 rows per block.
// Wh staged through SMEM 64-row tiles; P recomputed per tile; accumulation
// with packed fma.rn.f32x2 (2 MACs/instr, halves FMA-pipe pressure).
// Thread layout: fi = t&15 (feature quad), ii = (t>>4)&7 (row), jh = t>>7
// (j half, reduced 2-way at the end via SMEM).
// ---------------------------------------------------------------------------
__global__ __launch_bounds__(256) void gat_k2b(const int* __restrict__ adj,
                                               float* __restrict__ out) {
    __shared__ float Whs[64 * 64];       // tile: [jj][f]
    __shared__ float ps[8][65];          // padded against 2-way conflicts
    __shared__ float e2s[Nn];
    __shared__ float e1sh[8], msh[8], ish[8];
    __shared__ float4 red[128];

    int t = threadIdx.x;
    int r0 = blockIdx.x * 8;

#pragma unroll
    for (int k = 0; k < 1; k++)
        ((float4*)e2s)[t] = ((const float4*)g_e2)[t];   // 1024 floats
    if (t < 8) {
        e1sh[t] = g_e1[r0 + t];
        msh[t]  = g_m[r0 + t];
        ish[t]  = g_is[r0 + t];
    }
    __syncthreads();

    int fi = t & 15;
    int ii = (t >> 4) & 7;
    int jh = t >> 7;

    int pii = t >> 5;                    // p-compute mapping: 2 entries/thread
    int pjj = (t & 31) * 2;

    unsigned long long acc01 = 0ull, acc23 = 0ull;

#pragma unroll 1
    for (int jt = 0; jt < Nn / 64; jt++) {
        int j0 = jt * 64;
        const float4* src = (const float4*)(g_Wh + j0 * Ff);
#pragma unroll
        for (int k = 0; k < 4; k++)
            ((float4*)Whs)[t + k * 256] = src[t + k * 256];
        {
            int row = r0 + pii;
            int2 av = *(const int2*)(adj + (size_t)row * Nn + j0 + pjj);
            float2 e2p = *(const float2*)(&e2s[j0 + pjj]);
            float e1v = e1sh[pii], m = msh[pii], is = ish[pii];
            float sc0 = e1v + e2p.x;
            float sc1 = e1v + e2p.y;
            sc0 = (sc0 > 0.f) ? sc0 : LRELU_ALPHA * sc0; if (av.x <= 0) sc0 = NEG_INF;
            sc1 = (sc1 > 0.f) ? sc1 : LRELU_ALPHA * sc1; if (av.y <= 0) sc1 = NEG_INF;
            ps[pii][pjj]     = __expf(sc0 - m) * is;
            ps[pii][pjj + 1] = __expf(sc1 - m) * is;
        }
        __syncthreads();

        const ulonglong2* whrow = (const ulonglong2*)Whs;
#pragma unroll
        for (int k = 0; k < 32; k++) {
            int jj = jh * 32 + k;
            ulonglong2 wh = whrow[jj * 16 + fi];
            float p = ps[ii][jj];
            unsigned int pu = __float_as_uint(p);
            unsigned long long pp;
            asm("mov.b64 %0, {%1, %1};" : "=l"(pp) : "r"(pu));
            asm("fma.rn.f32x2 %0, %1, %2, %0;" : "+l"(acc01) : "l"(pp), "l"(wh.x));
            asm("fma.rn.f32x2 %0, %1, %2, %0;" : "+l"(acc23) : "l"(pp), "l"(wh.y));
        }
        __syncthreads();
    }

    float2 a01 = *(float2*)&acc01;
    float2 a23 = *(float2*)&acc23;
    float4 acc = make_float4(a01.x, a01.y, a23.x, a23.y);
    if (jh == 1) red[t - 128] = acc;
    __syncthreads();
    if (jh == 0) {
        float4 o = red[t];
        acc.x += o.x; acc.y += o.y; acc.z += o.z; acc.w += o.w;
        acc.x = (acc.x > 0.f) ? acc.x : expm1f(acc.x);
        acc.y = (acc.y > 0.f) ? acc.y : expm1f(acc.y);
        acc.z = (acc.z > 0.f) ? acc.z : expm1f(acc.z);
        acc.w = (acc.w > 0.f) ? acc.w : expm1f(acc.w);
        ((float4*)out)[(r0 + ii) * 16 + fi] = acc;
    }
}

// ---------------------------------------------------------------------------
extern "C" void kernel_launch(void* const* d_in, const int* in_sizes, int n_in,
                              void* d_out, int out_size) {
    const float* h   = (const float*)d_in[0];
    const int*   adj = (const int*)d_in[1];
    const float* W   = (const float*)d_in[2];
    const float* a   = (const float*)d_in[3];
    float* out = (float*)d_out;

    gat_k1<<<Nn / 16, 256>>>(h, W, a);
    gat_k2a<<<Nn, 256>>>(adj);
    gat_k2b<<<Nn / 8, 256>>>(adj, out);
}

// round 2
// speedup vs baseline: 1.1346x; 1.1346x over previous
#include <cuda_runtime.h>
#include <math.h>

#define Nn 1024
#define Ff 64
#define ALPHA 0.2f
#define NEG_INF -9000000000000000.0f

// scratch
__device__ float g_Wh[Nn * Ff];
__device__ float g_e1[Nn];
__device__ float g_e2[Nn];

// ---------------------------------------------------------------------------
// k1: Wh = h @ W ; e1 = Wh@a1 ; e2 = Wh@a2.
// grid 256 (4 rows/block), 256 threads, 1 output element per thread.
// ---------------------------------------------------------------------------
__global__ __launch_bounds__(256) void gat_k1(const float* __restrict__ h,
                                              const float* __restrict__ W,
                                              const float* __restrict__ a) {
    __shared__ float Ws[Ff * Ff];     // [k][f]
    __shared__ float hs[4 * Ff];
    __shared__ float a1s[Ff], a2s[Ff];
    __shared__ float es1[8], es2[8];
    int t = threadIdx.x;
    int row0 = blockIdx.x * 4;

#pragma unroll
    for (int k = 0; k < 4; k++)
        ((float4*)Ws)[t + k * 256] = ((const float4*)W)[t + k * 256];
    hs[t] = h[row0 * Ff + t];
    if (t < Ff) { a1s[t] = a[t]; a2s[t] = a[Ff + t]; }
    __syncthreads();

    int ii = t >> 6;          // 0..3
    int f  = t & 63;
    float acc = 0.f;
#pragma unroll
    for (int k = 0; k < Ff; k++)
        acc += hs[ii * Ff + k] * Ws[k * Ff + f];
    int row = row0 + ii;
    g_Wh[row * Ff + f] = acc;

    float p1 = acc * a1s[f];
    float p2 = acc * a2s[f];
#pragma unroll
    for (int o = 16; o; o >>= 1) {
        p1 += __shfl_xor_sync(0xffffffffu, p1, o);
        p2 += __shfl_xor_sync(0xffffffffu, p2, o);
    }
    int w = t >> 5;
    if ((t & 31) == 0) { es1[w] = p1; es2[w] = p2; }
    __syncthreads();
    if (t < 4) {
        g_e1[row0 + t] = es1[2 * t] + es1[2 * t + 1];
        g_e2[row0 + t] = es2[2 * t] + es2[2 * t + 1];
    }
}

// ---------------------------------------------------------------------------
// k2: fused softmax-stats + out = elu(P @ Wh).
// grid 128 (8 rows/block), 256 threads.
// Stage 1: warp w owns row r0+w; 32 scores/lane in registers -> m, 1/sum
//          stay in registers (xor reductions -> uniform in warp).
// Stage 2: 16 j-tiles of 64. Per tile: Wh tile -> SMEM, p tile recomputed
//          (adj row L1-hot). Thread (fi=t&15, jg=t>>4) accumulates an
//          8-row x 4-col register tile over its 64 j's with fma.rn.f32x2.
// Epilogue: 4-round SMEM tree reduction over the 16 j-splits (buffer
//          overlays the Wh tile), elu, store.
// ---------------------------------------------------------------------------
__global__ __launch_bounds__(256) void gat_k2(const int* __restrict__ adj,
                                              float* __restrict__ out) {
    __shared__ float Whs[64 * 68];    // Wh tile; reused as reduction buffer
    __shared__ float ps[8 * 68];      // p tile
    __shared__ float e2s[Nn];

    int t = threadIdx.x;
    int r0 = blockIdx.x * 8;
    int w = t >> 5, l = t & 31;
    int row = r0 + w;

    ((float4*)e2s)[t] = ((const float4*)g_e2)[t];
    __syncthreads();

    // ---- stage 1: row stats in registers ----
    float e1v = g_e1[row];
    float s[32];
    const int4* arow = (const int4*)(adj + (size_t)row * Nn);
#pragma unroll
    for (int k = 0; k < 8; k++) {
        int4 av = arow[l + k * 32];
        float4 e2v = ((const float4*)e2s)[l + k * 32];
        float s0 = e1v + e2v.x; s0 = (s0 > 0.f) ? s0 : ALPHA * s0; if (av.x <= 0) s0 = NEG_INF;
        float s1 = e1v + e2v.y; s1 = (s1 > 0.f) ? s1 : ALPHA * s1; if (av.y <= 0) s1 = NEG_INF;
        float s2 = e1v + e2v.z; s2 = (s2 > 0.f) ? s2 : ALPHA * s2; if (av.z <= 0) s2 = NEG_INF;
        float s3 = e1v + e2v.w; s3 = (s3 > 0.f) ? s3 : ALPHA * s3; if (av.w <= 0) s3 = NEG_INF;
        s[k * 4 + 0] = s0; s[k * 4 + 1] = s1; s[k * 4 + 2] = s2; s[k * 4 + 3] = s3;
    }
    float mx = s[0];
#pragma unroll
    for (int k = 1; k < 32; k++) mx = fmaxf(mx, s[k]);
#pragma unroll
    for (int o = 16; o; o >>= 1) mx = fmaxf(mx, __shfl_xor_sync(0xffffffffu, mx, o));
    float sum = 0.f;
#pragma unroll
    for (int k = 0; k < 32; k++) sum += __expf(s[k] - mx);
#pragma unroll
    for (int o = 16; o; o >>= 1) sum += __shfl_xor_sync(0xffffffffu, sum, o);
    float is = 1.0f / sum;

    // ---- stage 2: GEMM ----
    int fi = t & 15;
    int jg = t >> 4;
    unsigned long long acc_lo[8], acc_hi[8];
#pragma unroll
    for (int i = 0; i < 8; i++) { acc_lo[i] = 0ull; acc_hi[i] = 0ull; }

#pragma unroll 1
    for (int jt = 0; jt < Nn / 64; jt++) {
        int j0 = jt * 64;
        __syncthreads();   // guard reuse of Whs/ps vs previous tile's readers

        // load Wh tile [64][64] -> Whs[64][68]
        const float4* src = (const float4*)(g_Wh + j0 * Ff);
#pragma unroll
        for (int k = 0; k < 4; k++) {
            int idx = t + k * 256;         // 0..1023
            int r = idx >> 4, c4 = idx & 15;
            *(float4*)&Whs[r * 68 + c4 * 4] = src[idx];
        }
        // p tile: warp w -> its row; lane l -> jj = 2l, 2l+1 (adj L1-hot)
        {
            int jj = 2 * l;
            int2 av = *(const int2*)(adj + (size_t)row * Nn + j0 + jj);
            float2 e2p = *(const float2*)&e2s[j0 + jj];
            float sc0 = e1v + e2p.x; sc0 = (sc0 > 0.f) ? sc0 : ALPHA * sc0; if (av.x <= 0) sc0 = NEG_INF;
            float sc1 = e1v + e2p.y; sc1 = (sc1 > 0.f) ? sc1 : ALPHA * sc1; if (av.y <= 0) sc1 = NEG_INF;
            float2 pv;
            pv.x = __expf(sc0 - mx) * is;
            pv.y = __expf(sc1 - mx) * is;
            *(float2*)&ps[w * 68 + jj] = pv;
        }
        __syncthreads();

#pragma unroll
        for (int k = 0; k < 4; k++) {
            int jj = k * 16 + jg;
            float4 wh = *(const float4*)&Whs[jj * 68 + fi * 4];
            unsigned long long wlo, whi;
            asm("mov.b64 %0,{%1,%2};" : "=l"(wlo) : "r"(__float_as_uint(wh.x)), "r"(__float_as_uint(wh.y)));
            asm("mov.b64 %0,{%1,%2};" : "=l"(whi) : "r"(__float_as_uint(wh.z)), "r"(__float_as_uint(wh.w)));
#pragma unroll
            for (int ii = 0; ii < 8; ii++) {
                float p = ps[ii * 68 + jj];
                unsigned long long pp;
                asm("mov.b64 %0,{%1,%1};" : "=l"(pp) : "r"(__float_as_uint(p)));
                asm("fma.rn.f32x2 %0,%1,%2,%0;" : "+l"(acc_lo[ii]) : "l"(pp), "l"(wlo));
                asm("fma.rn.f32x2 %0,%1,%2,%0;" : "+l"(acc_hi[ii]) : "l"(pp), "l"(whi));
            }
        }
    }

    // unpack accumulators
    float af[8][4];
#pragma unroll
    for (int ii = 0; ii < 8; ii++) {
        float2 lo = *(float2*)&acc_lo[ii];
        float2 hi = *(float2*)&acc_hi[ii];
        af[ii][0] = lo.x; af[ii][1] = lo.y; af[ii][2] = hi.x; af[ii][3] = hi.y;
    }

    // ---- tree reduction over 16 jg splits (buffer overlays Whs) ----
    float* red = Whs;
    __syncthreads();
#pragma unroll
    for (int sh = 8; sh >= 1; sh >>= 1) {
        if (jg >= sh && jg < 2 * sh) {
            float4* dst = (float4*)&red[((jg - sh) * 16 + fi) * 32];
#pragma unroll
            for (int ii = 0; ii < 8; ii++)
                dst[ii] = make_float4(af[ii][0], af[ii][1], af[ii][2], af[ii][3]);
        }
        __syncthreads();
        if (jg < sh) {
            const float4* sp = (const float4*)&red[(jg * 16 + fi) * 32];
#pragma unroll
            for (int ii = 0; ii < 8; ii++) {
                float4 v = sp[ii];
                af[ii][0] += v.x; af[ii][1] += v.y; af[ii][2] += v.z; af[ii][3] += v.w;
            }
        }
        __syncthreads();
    }

    if (jg == 0) {
#pragma unroll
        for (int ii = 0; ii < 8; ii++) {
            float4 o;
            o.x = (af[ii][0] > 0.f) ? af[ii][0] : expm1f(af[ii][0]);
            o.y = (af[ii][1] > 0.f) ? af[ii][1] : expm1f(af[ii][1]);
            o.z = (af[ii][2] > 0.f) ? af[ii][2] : expm1f(af[ii][2]);
            o.w = (af[ii][3] > 0.f) ? af[ii][3] : expm1f(af[ii][3]);
            ((float4*)out)[(r0 + ii) * 16 + fi] = o;
        }
    }
}

// ---------------------------------------------------------------------------
extern "C" void kernel_launch(void* const* d_in, const int* in_sizes, int n_in,
                              void* d_out, int out_size) {
    const float* h   = (const float*)d_in[0];
    const int*   adj = (const int*)d_in[1];
    const float* W   = (const float*)d_in[2];
    const float* a   = (const float*)d_in[3];
    float* out = (float*)d_out;

    gat_k1<<<256, 256>>>(h, W, a);
    gat_k2<<<128, 256>>>(adj, out);
}